// round 9
// baseline (speedup 1.0000x reference)
#include <cuda_runtime.h>
#include <math.h>

// StatefulSynapseNet, R9: R8 GEMM structure (dual-sample warp, const-port
// weights, f32x2 FFMA, o-half splits) with the two samples INTERLEAVED as
// (A,B) f32x2 pairs through the H/y buffer, the IF+synapse scan, phase-2
// operands, and h2 — halving LDS/STS counts and packing scan arithmetic.

typedef unsigned long long ull;

__device__ __forceinline__ ull pack2(float lo, float hi) {
    ull r; asm("mov.b64 %0, {%1,%2};" : "=l"(r) : "f"(lo), "f"(hi)); return r;
}
__device__ __forceinline__ void unpack2(ull v, float& lo, float& hi) {
    asm("mov.b64 {%0,%1}, %2;" : "=f"(lo), "=f"(hi) : "l"(v));
}
__device__ __forceinline__ ull ffma2(ull a, ull b, ull c) {
    ull d; asm("fma.rn.f32x2 %0, %1, %2, %3;" : "=l"(d) : "l"(a), "l"(b), "l"(c)); return d;
}
__device__ __forceinline__ ull fadd2(ull a, ull b) {
    ull d; asm("add.rn.f32x2 %0, %1, %2;" : "=l"(d) : "l"(a), "l"(b)); return d;
}
__device__ __forceinline__ float set_ge(float a, float b) {
    float d; asm("set.ge.f32.f32 %0, %1, %2;" : "=f"(d) : "f"(a), "f"(b)); return d;
}

#define T_DIM 28
#define F_DIM 28
#define C1 32
#define C2 10
#define WARPS 4
#define SPW 2
#define YP2 66             // floats per t-row of interleaved y: 32 (A,B) pairs + pad
                           // 8B-word row stride = 33 (odd) -> conflict-free both ways
#define H2P2 29            // (A,B) pairs per j-row of h2 (28 + 1 pad)
#define REGION 1856        // 28*66 = 1848 floats, padded to 16B multiple

// constant-block layout (floats)
#define OFF_W1T 0          // [f*32 + o] = W1[o*28+f]
#define OFF_W2D 896        // o-dup W2: [j*64 + o*2 + c] = W2[j*32+o]
#define OFF_B1  1536       // 32
#define OFF_B2D 1568       // dup b2: [j*2 + c]
#define OFF_ITAU 1588
#define CP_SIZE 1600

__constant__ __align__(16) float c_P[CP_SIZE];
__device__   __align__(16) float g_stage[CP_SIZE];

__global__ void setup_kernel(const float* __restrict__ W1,
                             const float* __restrict__ b1,
                             const float* __restrict__ w_syn,
                             const float* __restrict__ W2,
                             const float* __restrict__ b2)
{
    int i = threadIdx.x;
    for (int idx = i; idx < C1 * F_DIM; idx += 1024) {
        int f = idx >> 5, o = idx & 31;
        g_stage[OFF_W1T + idx] = W1[o * F_DIM + f];
    }
    for (int idx = i; idx < C2 * C1 * 2; idx += 1024) {
        int jo = idx >> 1;                     // j*32 + o
        g_stage[OFF_W2D + ((jo >> 5) * 64) + ((jo & 31) * 2) + (idx & 1)] = W2[jo];
    }
    if (i < C1) g_stage[OFF_B1 + i] = b1[i];
    if (i < C2 * 2) g_stage[OFF_B2D + i] = b2[i >> 1];
    if (i == 0) g_stage[OFF_ITAU] = 1.0f / (1.0f + expf(-w_syn[0]));
}

__global__ __launch_bounds__(WARPS * 32, 7)
void snn_kernel(const float* __restrict__ x, float* __restrict__ out, int N)
{
    __shared__ float sh[WARPS * REGION];
    const int lane = threadIdx.x & 31;
    const int warp = threadIdx.x >> 5;
    const int n0 = (blockIdx.x * WARPS + warp) * SPW;
    if (n0 >= N) return;
    const bool has_b = (n0 + 1 < N);
    const int n1 = has_b ? (n0 + 1) : n0;

    float* shY = sh + warp * REGION;           // interleaved [t][o](A,B) pairs
    const bool tl = (lane < T_DIM);

    const float* xa = x + (size_t)n0 * (F_DIM * T_DIM) + lane;
    const float* xb = x + (size_t)n1 * (F_DIM * T_DIM) + lane;

    // ---- phase 1: lane = t, two o-halves (R8-proven const-port GEMM) ----
#pragma unroll
    for (int half = 0; half < 2; ++half) {
        ull accA[8], accB[8];
#pragma unroll
        for (int p = 0; p < 8; ++p) {
            ull b = *reinterpret_cast<const ull*>(c_P + OFF_B1 + half * 16 + 2 * p);
            accA[p] = b; accB[p] = b;
        }
#pragma unroll 7
        for (int f = 0; f < F_DIM; ++f) {
            float xva = tl ? __ldg(xa + f * T_DIM) : 0.0f;
            float xvb = tl ? __ldg(xb + f * T_DIM) : 0.0f;
            ull xpa = pack2(xva, xva);
            ull xpb = pack2(xvb, xvb);
            const ulonglong2* wq =
                reinterpret_cast<const ulonglong2*>(c_P + OFF_W1T + f * C1 + half * 16);
#pragma unroll
            for (int q = 0; q < 4; ++q) {
                ulonglong2 w = wq[q];
                accA[2 * q]     = ffma2(xpa, w.x, accA[2 * q]);
                accB[2 * q]     = ffma2(xpb, w.x, accB[2 * q]);
                accA[2 * q + 1] = ffma2(xpa, w.y, accA[2 * q + 1]);
                accB[2 * q + 1] = ffma2(xpb, w.y, accB[2 * q + 1]);
            }
        }
        // transpose to interleaved (A,B) pairs: 16 STS.64, conflict-free
        if (tl) {
            ull* yr = reinterpret_cast<ull*>(shY + lane * YP2);
#pragma unroll
            for (int p = 0; p < 8; ++p) {
                float a0, a1, b0, b1v;
                unpack2(accA[p], a0, a1);
                unpack2(accB[p], b0, b1v);
                yr[half * 16 + 2 * p]     = pack2(a0, b0);
                yr[half * 16 + 2 * p + 1] = pack2(a1, b1v);
            }
        }
    }
    __syncwarp();

    // ---- IF scan + synapse filter: lane = o, packed (A,B) state ----
    {
        const float itau = c_P[OFF_ITAU];
        const ull nitau2 = pack2(-itau, -itau);
        float va = 0.0f, vb = 0.0f;
        ull g2 = 0ULL;
#pragma unroll
        for (int t = 0; t < T_DIM; ++t) {
            ull hp = *reinterpret_cast<const ull*>(shY + t * YP2 + lane * 2);
            float ha, hb; unpack2(hp, ha, hb);
            va += ha;                           vb += hb;
            float sa = set_ge(va, 1.0f);        float sb = set_ge(vb, 1.0f);
            va = fmaf(va, -sa, va);             vb = fmaf(vb, -sb, vb);   // exact reset
            g2 = fadd2(ffma2(g2, nitau2, g2), pack2(sa, sb));             // g-g*itau+s
            *reinterpret_cast<ull*>(shY + t * YP2 + lane * 2) = g2;       // y[t][o](A,B)
        }
    }
    __syncwarp();

    // ---- phase 2: lane = t; y pairs are ready-made FFMA2 operands ----
    {
        ull pJ[C2];
#pragma unroll
        for (int j = 0; j < C2; ++j)
            pJ[j] = *reinterpret_cast<const ull*>(c_P + OFF_B2D + 2 * j);

        if (tl) {
            const ull* yr = reinterpret_cast<const ull*>(shY + lane * YP2);
#pragma unroll
            for (int half = 0; half < 2; ++half) {
                ull yq[16];
#pragma unroll
                for (int k = 0; k < 16; ++k) yq[k] = yr[half * 16 + k];
#pragma unroll
                for (int j = 0; j < C2; ++j) {
                    ull a = pJ[j];
                    const ulonglong2* wd = reinterpret_cast<const ulonglong2*>(
                        c_P + OFF_W2D + j * 64 + half * 32);
#pragma unroll
                    for (int q = 0; q < 8; ++q) {
                        ulonglong2 w = wd[q];
                        a = ffma2(yq[2 * q],     w.x, a);
                        a = ffma2(yq[2 * q + 1], w.y, a);
                    }
                    pJ[j] = a;
                }
            }
        }
        __syncwarp();                           // all y reads done -> overlay h2

        if (tl) {
            ull* hh = reinterpret_cast<ull*>(shY);
#pragma unroll
            for (int j = 0; j < C2; ++j)
                hh[j * H2P2 + lane] = pJ[j];    // h2[j][t] as (A,B) pairs
        }
    }
    __syncwarp();

    // ---- second IF scan + mean: 20 lanes (sj, ss); bank-conflict-free ----
    {
        int ss = (lane >= C2) ? 1 : 0;
        int sj = lane - ss * C2;
        if (lane < 2 * C2 && (ss == 0 || has_b)) {
            const float* hh = shY;
            float v = 0.0f, cnt = 0.0f;
#pragma unroll
            for (int t = 0; t < T_DIM; ++t) {
                v += hh[(sj * H2P2 + t) * 2 + ss];
                float s = set_ge(v, 1.0f);
                cnt += s;
                v = fmaf(v, -s, v);
            }
            int nn = ss ? n1 : n0;
            out[(size_t)nn * C2 + sj] = cnt * (1.0f / 28.0f);
        }
    }
}

extern "C" void kernel_launch(void* const* d_in, const int* in_sizes, int n_in,
                              void* d_out, int out_size)
{
    const float* x     = (const float*)d_in[0];
    const float* W1    = (const float*)d_in[1];
    const float* b1    = (const float*)d_in[2];
    const float* w_syn = (const float*)d_in[3];
    const float* W2    = (const float*)d_in[4];
    const float* b2    = (const float*)d_in[5];
    float* out = (float*)d_out;

    const int N = in_sizes[0] / (F_DIM * T_DIM);

    setup_kernel<<<1, 1024>>>(W1, b1, w_syn, W2, b2);

    void* sp = nullptr;
    cudaGetSymbolAddress(&sp, g_stage);
    cudaMemcpyToSymbolAsync(c_P, sp, CP_SIZE * sizeof(float), 0,
                            cudaMemcpyDeviceToDevice, 0);

    const int spb = WARPS * SPW;
    const int blocks = (N + spb - 1) / spb;
    snn_kernel<<<blocks, WARPS * 32>>>(x, out, N);
}

// round 10
// speedup vs baseline: 1.2900x; 1.2900x over previous
#include <cuda_runtime.h>
#include <math.h>

// StatefulSynapseNet, R10: R8 structure exactly (dual-sample warp, const-port
// weights, f32x2 FFMA GEMMs split in two o-halves, scalar pitch-33
// transposes, h2 overlay) with predication trimmed: clamped x pointers
// (no per-load selects) and set.ge+FFMA spike/reset logic in both scans.

typedef unsigned long long ull;

__device__ __forceinline__ ull pack2(float lo, float hi) {
    ull r; asm("mov.b64 %0, {%1,%2};" : "=l"(r) : "f"(lo), "f"(hi)); return r;
}
__device__ __forceinline__ void unpack2(ull v, float& lo, float& hi) {
    asm("mov.b64 {%0,%1}, %2;" : "=f"(lo), "=f"(hi) : "l"(v));
}
__device__ __forceinline__ ull ffma2(ull a, ull b, ull c) {
    ull d; asm("fma.rn.f32x2 %0, %1, %2, %3;" : "=l"(d) : "l"(a), "l"(b), "l"(c)); return d;
}
__device__ __forceinline__ float set_ge(float a, float b) {
    float d; asm("set.ge.f32.f32 %0, %1, %2;" : "=f"(d) : "f"(a), "f"(b)); return d;
}

#define T_DIM 28
#define F_DIM 28
#define C1 32
#define C2 10
#define WARPS 4
#define SPW 2
#define HP 33              // H/y pitch, conflict-free scalar pattern (proven)
#define H2P 29
#define REGION 928         // 28*33 = 924 floats, padded to 16B multiple

// constant-block layout (floats) — identical to R6/R8
#define OFF_W1T 0          // [f*32 + o] = W1[o*28+f]
#define OFF_W2  896        // [j*32 + o]
#define OFF_B1  1216
#define OFF_B2  1248
#define OFF_ITAU 1258
#define CP_SIZE 1280

__constant__ __align__(16) float c_P[CP_SIZE];
__device__   __align__(16) float g_stage[CP_SIZE];

__global__ void setup_kernel(const float* __restrict__ W1,
                             const float* __restrict__ b1,
                             const float* __restrict__ w_syn,
                             const float* __restrict__ W2,
                             const float* __restrict__ b2)
{
    int i = threadIdx.x;
    for (int idx = i; idx < C1 * F_DIM; idx += 1024) {
        int f = idx >> 5, o = idx & 31;
        g_stage[OFF_W1T + idx] = W1[o * F_DIM + f];
    }
    for (int idx = i; idx < C2 * C1; idx += 1024)
        g_stage[OFF_W2 + idx] = W2[idx];
    if (i < C1) g_stage[OFF_B1 + i] = b1[i];
    if (i < C2) g_stage[OFF_B2 + i] = b2[i];
    if (i == 0) g_stage[OFF_ITAU] = 1.0f / (1.0f + expf(-w_syn[0]));
}

__global__ __launch_bounds__(WARPS * 32, 7)
void snn_kernel(const float* __restrict__ x, float* __restrict__ out, int N)
{
    __shared__ float sh[WARPS * SPW * REGION];
    const int lane = threadIdx.x & 31;
    const int warp = threadIdx.x >> 5;
    const int n0 = (blockIdx.x * WARPS + warp) * SPW;
    if (n0 >= N) return;
    const bool has_b = (n0 + 1 < N);
    const int n1 = has_b ? (n0 + 1) : n0;

    float* shA = sh + warp * (SPW * REGION);   // H/y [t][o] pitch 33; h2 overlays
    float* shB = shA + REGION;
    const bool tl = (lane < T_DIM);
    const int t_eff = (lane < T_DIM) ? lane : (T_DIM - 1);   // clamp: loads unconditional

    const float* xa = x + (size_t)n0 * (F_DIM * T_DIM) + t_eff;
    const float* xb = x + (size_t)n1 * (F_DIM * T_DIM) + t_eff;

    // ---- phase 1: lane = t, two o-halves; acc = 8 ull per sample per half ----
#pragma unroll
    for (int half = 0; half < 2; ++half) {
        ull accA[8], accB[8];
#pragma unroll
        for (int p = 0; p < 8; ++p) {
            ull b = *reinterpret_cast<const ull*>(c_P + OFF_B1 + half * 16 + 2 * p);
            accA[p] = b; accB[p] = b;
        }
#pragma unroll 7
        for (int f = 0; f < F_DIM; ++f) {
            float xva = __ldg(xa + f * T_DIM);           // always in-bounds (clamped)
            float xvb = __ldg(xb + f * T_DIM);
            ull xpa = pack2(xva, xva);
            ull xpb = pack2(xvb, xvb);
            const ulonglong2* wq =
                reinterpret_cast<const ulonglong2*>(c_P + OFF_W1T + f * C1 + half * 16);
#pragma unroll
            for (int q = 0; q < 4; ++q) {                // each const load feeds 4 FFMA2
                ulonglong2 w = wq[q];
                accA[2 * q]     = ffma2(xpa, w.x, accA[2 * q]);
                accB[2 * q]     = ffma2(xpb, w.x, accB[2 * q]);
                accA[2 * q + 1] = ffma2(xpa, w.y, accA[2 * q + 1]);
                accB[2 * q + 1] = ffma2(xpb, w.y, accB[2 * q + 1]);
            }
        }
        if (tl) {                                        // stores guarded (region safety)
#pragma unroll
            for (int p = 0; p < 8; ++p) {
                float a0, a1, b0, b1v;
                unpack2(accA[p], a0, a1);
                unpack2(accB[p], b0, b1v);
                shA[lane * HP + half * 16 + 2 * p]     = a0;
                shA[lane * HP + half * 16 + 2 * p + 1] = a1;
                shB[lane * HP + half * 16 + 2 * p]     = b0;
                shB[lane * HP + half * 16 + 2 * p + 1] = b1v;
            }
        }
    }
    __syncwarp();

    // ---- IF scan + synapse filter: lane = o (all 32 live), set_ge + FFMA reset ----
    {
        const float itau = c_P[OFF_ITAU];
        float va = 0.0f, ga = 0.0f, vb = 0.0f, gb = 0.0f;
#pragma unroll
        for (int t = 0; t < T_DIM; ++t) {
            float ha = shA[t * HP + lane];
            float hb = shB[t * HP + lane];
            va += ha;                             vb += hb;
            float sa = set_ge(va, 1.0f);          float sb = set_ge(vb, 1.0f);
            va = fmaf(va, -sa, va);               vb = fmaf(vb, -sb, vb);   // exact reset
            ga = fmaf(ga, -itau, ga) + sa;        gb = fmaf(gb, -itau, gb) + sb;
            shA[t * HP + lane] = ga;
            shB[t * HP + lane] = gb;
        }
    }
    __syncwarp();

    // ---- phase 2: lane = t, two o-halves, scalar partials; h2 overlays y ----
    {
        float pA[C2], pB[C2];
#pragma unroll
        for (int j = 0; j < C2; ++j) { pA[j] = 0.0f; pB[j] = 0.0f; }

        if (tl) {
#pragma unroll
            for (int half = 0; half < 2; ++half) {
                ull yqa[8], yqb[8];
                const float* ya = shA + lane * HP + half * 16;
                const float* yb = shB + lane * HP + half * 16;
#pragma unroll
                for (int q = 0; q < 8; ++q) {
                    yqa[q] = pack2(ya[2 * q], ya[2 * q + 1]);
                    yqb[q] = pack2(yb[2 * q], yb[2 * q + 1]);
                }
#pragma unroll
                for (int j = 0; j < C2; ++j) {
                    ull a2 = 0ULL, b2a = 0ULL;
                    const ulonglong2* wq2 =
                        reinterpret_cast<const ulonglong2*>(c_P + OFF_W2 + j * C1 + half * 16);
#pragma unroll
                    for (int q = 0; q < 4; ++q) {
                        ulonglong2 w = wq2[q];
                        a2  = ffma2(yqa[2 * q],     w.x, a2);
                        b2a = ffma2(yqb[2 * q],     w.x, b2a);
                        a2  = ffma2(yqa[2 * q + 1], w.y, a2);
                        b2a = ffma2(yqb[2 * q + 1], w.y, b2a);
                    }
                    float u0, u1, v0, v1;
                    unpack2(a2, u0, u1);
                    unpack2(b2a, v0, v1);
                    pA[j] += u0 + u1;
                    pB[j] += v0 + v1;
                }
            }
        }
        __syncwarp();                          // all y reads done -> overlay h2

        if (tl) {
#pragma unroll
            for (int j = 0; j < C2; ++j) {
                float bj = c_P[OFF_B2 + j];
                shA[j * H2P + lane] = pA[j] + bj;   // h2 overlays y region
                shB[j * H2P + lane] = pB[j] + bj;
            }
        }
    }
    __syncwarp();

    // ---- second IF scan + mean: 20 lanes (j = lane&15, sample = lane>>4) ----
    {
        int sj = lane & 15;
        int ss = lane >> 4;
        if (sj < C2 && (ss == 0 || has_b)) {
            const float* h2 = ss ? shB : shA;
            float v = 0.0f, cnt = 0.0f;
#pragma unroll
            for (int t = 0; t < T_DIM; ++t) {
                v += h2[sj * H2P + t];
                float s = set_ge(v, 1.0f);
                cnt += s;
                v = fmaf(v, -s, v);            // exact reset
            }
            int nn = ss ? n1 : n0;
            out[(size_t)nn * C2 + sj] = cnt * (1.0f / 28.0f);
        }
    }
}

extern "C" void kernel_launch(void* const* d_in, const int* in_sizes, int n_in,
                              void* d_out, int out_size)
{
    const float* x     = (const float*)d_in[0];
    const float* W1    = (const float*)d_in[1];
    const float* b1    = (const float*)d_in[2];
    const float* w_syn = (const float*)d_in[3];
    const float* W2    = (const float*)d_in[4];
    const float* b2    = (const float*)d_in[5];
    float* out = (float*)d_out;

    const int N = in_sizes[0] / (F_DIM * T_DIM);

    setup_kernel<<<1, 1024>>>(W1, b1, w_syn, W2, b2);

    void* sp = nullptr;
    cudaGetSymbolAddress(&sp, g_stage);
    cudaMemcpyToSymbolAsync(c_P, sp, CP_SIZE * sizeof(float), 0,
                            cudaMemcpyDeviceToDevice, 0);

    const int spb = WARPS * SPW;
    const int blocks = (N + spb - 1) / spb;
    snn_kernel<<<blocks, WARPS * 32>>>(x, out, N);
}